// round 9
// baseline (speedup 1.0000x reference)
#include <cuda_runtime.h>
#include <cuda_fp16.h>
#include <math.h>
#include <stdint.h>

#define BATCH 8
#define NINST 8192
#define DIM   512
#define HID   64
#define TOPK_K 2457

#define GCHUNKS 64
#define GROWS   (NINST / GCHUNKS)   // 128

#define KCHUNKS 16
#define KLEN    (DIM / KCHUNKS)     // 32

// attn tiling
#define BM 128
#define BN 64
#define BK 32
#define NCH (DIM / BK)              // 16

#define CAP  512
#define BAND 4e-4f

// scratch (device globals; no allocation allowed)
__device__ __align__(16) __half g_w1h[DIM * HID];  // aW1 fp16, [k][n]
__device__ float    g_part[GCHUNKS * BATCH * DIM];
__device__ float    g_p1[KCHUNKS * BATCH * DIM];
__device__ float    g_p2[KCHUNKS * BATCH * DIM];
__device__ unsigned g_thr[BATCH];                 // approx kth weight (bits)
__device__ int      g_above[BATCH];               // #(w > thr+BAND)
__device__ int      g_ccnt[BATCH];                // candidate count
__device__ int      g_cand[BATCH][CAP];           // candidate indices
__device__ unsigned char g_flag[BATCH * NINST];   // boundary-selected flags

__device__ __forceinline__ float gelu_f(float v) {
    float u = 0.7978845608028654f * (v + 0.044715f * v * v * v);
    return 0.5f * v * (1.0f + tanhf(u));
}

__device__ __forceinline__ void cp16(uint32_t sdst, const void* gsrc) {
    asm volatile("cp.async.cg.shared.global [%0], [%1], 16;" :: "r"(sdst), "l"(gsrc));
}

__device__ __forceinline__ void hmma(float* c, const unsigned* a, const unsigned* b) {
    asm volatile(
        "mma.sync.aligned.m16n8k16.row.col.f32.f16.f16.f32 "
        "{%0,%1,%2,%3}, {%4,%5,%6,%7}, {%8,%9}, {%0,%1,%2,%3};"
        : "+f"(c[0]), "+f"(c[1]), "+f"(c[2]), "+f"(c[3])
        : "r"(a[0]), "r"(a[1]), "r"(a[2]), "r"(a[3]), "r"(b[0]), "r"(b[1]));
}

__device__ __forceinline__ void ldm_x4(unsigned* r, uint32_t addr) {
    asm volatile("ldmatrix.sync.aligned.m8n8.x4.shared.b16 {%0,%1,%2,%3}, [%4];"
                 : "=r"(r[0]), "=r"(r[1]), "=r"(r[2]), "=r"(r[3]) : "r"(addr));
}
__device__ __forceinline__ void ldm_x4t(unsigned* r, uint32_t addr) {
    asm volatile("ldmatrix.sync.aligned.m8n8.x4.trans.shared.b16 {%0,%1,%2,%3}, [%4];"
                 : "=r"(r[0]), "=r"(r[1]), "=r"(r[2]), "=r"(r[3]) : "r"(addr));
}

// ---------------------------------------------------------------------------
// Kernel 0: round aW1 to fp16.
// ---------------------------------------------------------------------------
__global__ __launch_bounds__(256) void conv_w1_kernel(const float* __restrict__ aW1)
{
    int i = blockIdx.x * 256 + threadIdx.x;
    if (i < DIM * HID)
        g_w1h[i] = __float2half_rn(aW1[i]);
}

// ---------------------------------------------------------------------------
// Kernel 1: fused attention-score MLP, fp16 HMMA 2-term (A = hi+lo, B = fp16).
// (unchanged from R8 — validated)
// ---------------------------------------------------------------------------
__global__ __launch_bounds__(256) void attn_kernel(
    const float* __restrict__ x,
    const float* __restrict__ ab1,
    const float* __restrict__ aW2,
    const float* __restrict__ ab2,
    float* __restrict__ wout)
{
    __shared__ __align__(16) __half Ah[BM][40];
    __shared__ __align__(16) __half Al[BM][40];
    __shared__ __align__(16) __half Bh[2][BK][72];
    __shared__ float red[128][2];

    const int tid   = threadIdx.x;
    const int lane  = tid & 31;
    const int warp  = tid >> 5;
    const int warpM = warp >> 1;
    const int warpN = warp & 1;
    const long rowBase = (long)blockIdx.x * BM;
    const float* xb = x + rowBase * DIM;

    float acc[2][4][4];
    #pragma unroll
    for (int mi = 0; mi < 2; mi++)
        #pragma unroll
        for (int ni = 0; ni < 4; ni++)
            #pragma unroll
            for (int q = 0; q < 4; q++) acc[mi][ni][q] = 0.f;

    auto loadB = [&](int s, int c) {
        int r = tid >> 3, g = tid & 7;
        uint32_t dh = (uint32_t)__cvta_generic_to_shared(&Bh[s][r][g * 8]);
        cp16(dh, g_w1h + (c * BK + r) * HID + g * 8);
        asm volatile("cp.async.commit_group;");
    };

    const int ar = tid >> 1;
    const int ah = tid & 1;
    const float* xrow = xb + (long)ar * DIM + ah * 16;

    loadB(0, 0);
    float4 xr[4];
    #pragma unroll
    for (int q = 0; q < 4; q++)
        xr[q] = *reinterpret_cast<const float4*>(xrow + q * 4);

    for (int c = 0; c < NCH; c++) {
        unsigned hw[8], lw[8];
        const float* xv = reinterpret_cast<const float*>(xr);
        #pragma unroll
        for (int e = 0; e < 8; e++) {
            float v0 = xv[2 * e], v1 = xv[2 * e + 1];
            __half h0 = __float2half_rn(v0);
            __half l0 = __float2half_rn(v0 - __half2float(h0));
            __half h1 = __float2half_rn(v1);
            __half l1 = __float2half_rn(v1 - __half2float(h1));
            __half2 hp = __halves2half2(h0, h1);
            __half2 lp = __halves2half2(l0, l1);
            hw[e] = *reinterpret_cast<unsigned*>(&hp);
            lw[e] = *reinterpret_cast<unsigned*>(&lp);
        }
        float4 xn[4];
        if (c + 1 < NCH) {
            #pragma unroll
            for (int q = 0; q < 4; q++)
                xn[q] = *reinterpret_cast<const float4*>(xrow + (c + 1) * BK + q * 4);
        }
        __syncthreads();

        {
            char* pa = reinterpret_cast<char*>(&Ah[0][0]) + ar * 80 + ah * 32;
            char* pl = reinterpret_cast<char*>(&Al[0][0]) + ar * 80 + ah * 32;
            *reinterpret_cast<uint4*>(pa)      = make_uint4(hw[0], hw[1], hw[2], hw[3]);
            *reinterpret_cast<uint4*>(pa + 16) = make_uint4(hw[4], hw[5], hw[6], hw[7]);
            *reinterpret_cast<uint4*>(pl)      = make_uint4(lw[0], lw[1], lw[2], lw[3]);
            *reinterpret_cast<uint4*>(pl + 16) = make_uint4(lw[4], lw[5], lw[6], lw[7]);
        }
        if (c + 1 < NCH) {
            loadB((c + 1) & 1, c + 1);
            asm volatile("cp.async.wait_group 1;");
        } else {
            asm volatile("cp.async.wait_group 0;");
        }
        __syncthreads();

        const int st = c & 1;
        #pragma unroll
        for (int ks = 0; ks < 2; ks++) {
            const int k0 = ks * 16;
            unsigned Ahf[2][4], Alf[2][4];
            #pragma unroll
            for (int mi = 0; mi < 2; mi++) {
                int arow2 = warpM * 32 + mi * 16 + (lane & 15);
                int acol  = k0 + ((lane >> 4) << 3);
                uint32_t base = (uint32_t)__cvta_generic_to_shared(&Ah[arow2][acol]);
                ldm_x4(Ahf[mi], base);
                uint32_t basel = (uint32_t)__cvta_generic_to_shared(&Al[arow2][acol]);
                ldm_x4(Alf[mi], basel);
            }
            unsigned Bhf[4][2];
            #pragma unroll
            for (int pr = 0; pr < 2; pr++) {
                int brow = k0 + (lane & 15);
                int bcol = warpN * 32 + pr * 16 + ((lane >> 4) << 3);
                unsigned t4[4];
                uint32_t bb = (uint32_t)__cvta_generic_to_shared(&Bh[st][brow][bcol]);
                ldm_x4t(t4, bb);
                Bhf[pr * 2][0] = t4[0]; Bhf[pr * 2][1] = t4[1];
                Bhf[pr * 2 + 1][0] = t4[2]; Bhf[pr * 2 + 1][1] = t4[3];
            }
            #pragma unroll
            for (int mi = 0; mi < 2; mi++)
                #pragma unroll
                for (int ni = 0; ni < 4; ni++) {
                    hmma(acc[mi][ni], Ahf[mi], Bhf[ni]);
                    hmma(acc[mi][ni], Alf[mi], Bhf[ni]);
                }
        }
        #pragma unroll
        for (int q = 0; q < 4; q++) xr[q] = xn[q];
    }

    const int lk = lane & 3;
    const int lr = lane >> 2;
    float b1v[4][2], w2v[4][2];
    #pragma unroll
    for (int ni = 0; ni < 4; ni++) {
        int col = warpN * 32 + ni * 8 + 2 * lk;
        b1v[ni][0] = ab1[col];     b1v[ni][1] = ab1[col + 1];
        w2v[ni][0] = aW2[col];     w2v[ni][1] = aW2[col + 1];
    }
    float p[2][2] = {{0.f, 0.f}, {0.f, 0.f}};
    #pragma unroll
    for (int mi = 0; mi < 2; mi++)
        #pragma unroll
        for (int ni = 0; ni < 4; ni++) {
            p[mi][0] += gelu_f(acc[mi][ni][0] + b1v[ni][0]) * w2v[ni][0]
                      + gelu_f(acc[mi][ni][1] + b1v[ni][1]) * w2v[ni][1];
            p[mi][1] += gelu_f(acc[mi][ni][2] + b1v[ni][0]) * w2v[ni][0]
                      + gelu_f(acc[mi][ni][3] + b1v[ni][1]) * w2v[ni][1];
        }
    #pragma unroll
    for (int mi = 0; mi < 2; mi++)
        #pragma unroll
        for (int h = 0; h < 2; h++) {
            p[mi][h] += __shfl_xor_sync(0xffffffffu, p[mi][h], 1);
            p[mi][h] += __shfl_xor_sync(0xffffffffu, p[mi][h], 2);
        }
    if (lk == 0) {
        #pragma unroll
        for (int mi = 0; mi < 2; mi++) {
            int r = warpM * 32 + mi * 16 + lr;
            red[r][warpN]     = p[mi][0];
            red[r + 8][warpN] = p[mi][1];
        }
    }
    __syncthreads();
    if (tid < 128) {
        float s = red[tid][0] + red[tid][1] + ab2[0];
        wout[rowBase + tid] = 1.0f / (1.0f + expf(-s));
    }
}

// ---------------------------------------------------------------------------
// Kernel 2: radix-select kth value + band candidate collection + flag reset.
// ---------------------------------------------------------------------------
__global__ __launch_bounds__(512) void select_kernel(const float* __restrict__ w)
{
    __shared__ unsigned sv[NINST];
    __shared__ int hist[16][256];
    __shared__ unsigned s_prefix;
    __shared__ int s_k, s_above, s_cnt;

    const int b = blockIdx.x;
    const int tid = threadIdx.x;
    const int wid = tid >> 5;
    const float* wb = w + b * NINST;

    for (int i = tid; i < NINST; i += 512)
        sv[i] = __float_as_uint(wb[i]);
    if (tid == 0) { s_prefix = 0u; s_k = TOPK_K; s_above = 0; s_cnt = 0; }
    __syncthreads();

    for (int r = 0; r < 4; r++) {
        for (int i = tid; i < 16 * 256; i += 512)
            hist[i >> 8][i & 255] = 0;
        __syncthreads();
        const unsigned pref = s_prefix;
        const int sh = 24 - 8 * r;
        for (int i = tid; i < NINST; i += 512) {
            unsigned v = sv[i];
            bool ok = (r == 0) || ((v >> (sh + 8)) == pref);
            if (ok) atomicAdd(&hist[wid][(v >> sh) & 255], 1);
        }
        __syncthreads();
        if (tid < 256) {
            int s = hist[0][tid];
            #pragma unroll
            for (int h = 1; h < 16; h++) s += hist[h][tid];
            hist[0][tid] = s;
        }
        __syncthreads();
        if (tid == 0) {
            int k = s_k, cum = 0, bsel = 0;
            for (int bb = 255; bb >= 0; --bb) {
                cum += hist[0][bb];
                if (cum >= k) { bsel = bb; s_k = k - (cum - hist[0][bb]); break; }
            }
            s_prefix = (pref << 8) | (unsigned)bsel;
        }
        __syncthreads();
    }

    const float t   = __uint_as_float(s_prefix);
    const float thi = t + BAND;
    const float tlo = t - BAND;

    int la = 0;
    for (int i = tid; i < NINST; i += 512) {
        float wv = __uint_as_float(sv[i]);
        g_flag[b * NINST + i] = 0;
        if (wv > thi) la++;
        else if (wv >= tlo) {
            int p = atomicAdd(&s_cnt, 1);
            if (p < CAP) g_cand[b][p] = i;
        }
    }
    atomicAdd(&s_above, la);
    __syncthreads();
    if (tid == 0) {
        g_thr[b]   = s_prefix;
        g_above[b] = s_above;
        g_ccnt[b]  = s_cnt < CAP ? s_cnt : CAP;
    }
}

// ---------------------------------------------------------------------------
// Kernel 3: fused refine + finalize. One block per batch, 16 warps.
// Each warp owns a candidate: stage x-row in its smem slab, exact fp32
// score, value into shared v[]. Then block-wide exact ranking -> flags.
// ---------------------------------------------------------------------------
__global__ __launch_bounds__(512) void refine_finalize_kernel(
    const float* __restrict__ x,  const float* __restrict__ aW1,
    const float* __restrict__ ab1, const float* __restrict__ aW2,
    const float* __restrict__ ab2)
{
    __shared__ float sx[16][DIM];
    __shared__ float v[CAP];
    __shared__ int  ix[CAP];

    const int b    = blockIdx.x;
    const int tid  = threadIdx.x;
    const int wrp  = tid >> 5;
    const int lane = tid & 31;
    const int cnt  = g_ccnt[b];
    const int need = TOPK_K - g_above[b];

    for (int ci = wrp; ci < cnt; ci += 16) {
        const int idx = g_cand[b][ci];
        const float* xr = x + ((long)b * NINST + idx) * DIM;
        #pragma unroll
        for (int it = 0; it < DIM / 32; it++)
            sx[wrp][it * 32 + lane] = xr[it * 32 + lane];
        __syncwarp();

        // lane handles hidden units j=lane and j=lane+32
        float a0 = 0.f, a1 = 0.f;
        const float* w0 = aW1 + lane;
        const float* w1 = aW1 + lane + 32;
        #pragma unroll 8
        for (int d = 0; d < DIM; d++) {
            float xv = sx[wrp][d];
            a0 += xv * w0[(long)d * HID];
            a1 += xv * w1[(long)d * HID];
        }
        float hv = gelu_f(a0 + ab1[lane])      * aW2[lane]
                 + gelu_f(a1 + ab1[lane + 32]) * aW2[lane + 32];
        #pragma unroll
        for (int off = 16; off >= 1; off >>= 1)
            hv += __shfl_down_sync(0xffffffffu, hv, off);
        if (lane == 0) {
            float logit = hv + ab2[0];
            v[ci]  = 1.0f / (1.0f + expf(-logit));
            ix[ci] = idx;
        }
    }
    __syncthreads();

    // exact ranking (value desc, index asc) -> flag top 'need'
    for (int i = tid; i < cnt; i += 512) {
        float vi = v[i]; int xi = ix[i];
        int rank = 0;
        for (int j = 0; j < cnt; j++)
            rank += (v[j] > vi) || (v[j] == vi && ix[j] < xi);
        if (rank < need) g_flag[b * NINST + xi] = 1;
    }
}

// ---------------------------------------------------------------------------
// Kernel 4: weighted gather-sum with per-block index compaction.
// Ascending order within chunk preserved -> identical sum order.
// ---------------------------------------------------------------------------
__global__ __launch_bounds__(128) void gather_kernel(
    const float* __restrict__ x, const float* __restrict__ w)
{
    __shared__ int   sel[GROWS];
    __shared__ float sw[GROWS];
    __shared__ int   wbase[4];
    __shared__ int   scount;

    const int b  = blockIdx.y;
    const int rc = blockIdx.x;
    const int r0 = rc * GROWS;
    const int tid = threadIdx.x;
    const int lane = tid & 31;
    const int wrp = tid >> 5;

    const float thi = __uint_as_float(g_thr[b]) + BAND;

    // phase A: compact selected rows (one row per thread, GROWS == 128)
    float wi = w[b * NINST + r0 + tid];
    bool pick = (wi > thi) || g_flag[b * NINST + r0 + tid];
    unsigned mask = __ballot_sync(0xffffffffu, pick);
    int wcnt = __popc(mask);
    if (lane == 0) wbase[wrp] = wcnt;
    __syncthreads();
    if (tid == 0) {
        int s = 0;
        #pragma unroll
        for (int q = 0; q < 4; q++) { int c = wbase[q]; wbase[q] = s; s += c; }
        scount = s;
    }
    __syncthreads();
    if (pick) {
        int pos = wbase[wrp] + __popc(mask & ((1u << lane) - 1u));
        sel[pos] = tid;
        sw[pos]  = wi;
    }
    __syncthreads();

    // phase B: sum only selected rows, 128 threads cover 512 dims (float4)
    const int d4 = tid * 4;
    const int nsel = scount;
    const float* xb = x + ((long)b * NINST + r0) * DIM + d4;

    float4 acc = make_float4(0.f, 0.f, 0.f, 0.f);
    for (int s = 0; s < nsel; s++) {
        float ws = sw[s];
        float4 xv = *reinterpret_cast<const float4*>(xb + (long)sel[s] * DIM);
        acc.x += ws * xv.x; acc.y += ws * xv.y;
        acc.z += ws * xv.z; acc.w += ws * xv.w;
    }
    *reinterpret_cast<float4*>(&g_part[(rc * BATCH + b) * DIM + d4]) = acc;
}

// ---------------------------------------------------------------------------
// Kernel 5: mlp1 split-K partials with inline emb reduction.
// ---------------------------------------------------------------------------
__global__ __launch_bounds__(128) void mlp1_part_kernel(
    const float* __restrict__ W, float* __restrict__ part)
{
    __shared__ float s_in[BATCH][KLEN];
    const int kc = blockIdx.y;
    const int j  = blockIdx.x * 128 + threadIdx.x;

    #pragma unroll
    for (int it = 0; it < (BATCH * KLEN) / 128; it++) {
        int i = it * 128 + threadIdx.x;
        int bb = i / KLEN, dd = i % KLEN;
        const float* p = g_part + bb * DIM + kc * KLEN + dd;
        float s0 = 0.f, s1 = 0.f;
        #pragma unroll
        for (int rc = 0; rc < GCHUNKS; rc += 2) {
            s0 += p[(long)rc * BATCH * DIM];
            s1 += p[(long)(rc + 1) * BATCH * DIM];
        }
        s_in[bb][dd] = (s0 + s1) * (1.0f / (float)TOPK_K);
    }
    __syncthreads();

    float acc[BATCH];
    #pragma unroll
    for (int bb = 0; bb < BATCH; bb++) acc[bb] = 0.f;

    #pragma unroll 4
    for (int dd = 0; dd < KLEN; dd++) {
        float wv = W[(long)(kc * KLEN + dd) * DIM + j];
        #pragma unroll
        for (int bb = 0; bb < BATCH; bb++)
            acc[bb] += s_in[bb][dd] * wv;
    }
    #pragma unroll
    for (int bb = 0; bb < BATCH; bb++)
        part[(kc * BATCH + bb) * DIM + j] = acc[bb];
}

// ---------------------------------------------------------------------------
// Kernel 6: mlp2 split-K partials with inline (reduce p1 + bias + gelu).
// ---------------------------------------------------------------------------
__global__ __launch_bounds__(128) void mlp2_part_kernel(
    const float* __restrict__ W, const float* __restrict__ b1,
    float* __restrict__ part)
{
    __shared__ float s_in[BATCH][KLEN];
    const int kc = blockIdx.y;
    const int j  = blockIdx.x * 128 + threadIdx.x;

    #pragma unroll
    for (int it = 0; it < (BATCH * KLEN) / 128; it++) {
        int i = it * 128 + threadIdx.x;
        int bb = i / KLEN, dd = i % KLEN;
        const float* p = g_p1 + bb * DIM + kc * KLEN + dd;
        float s = 0.f;
        #pragma unroll
        for (int c = 0; c < KCHUNKS; c++)
            s += p[(long)c * BATCH * DIM];
        s_in[bb][dd] = gelu_f(s + b1[kc * KLEN + dd]);
    }
    __syncthreads();

    float acc[BATCH];
    #pragma unroll
    for (int bb = 0; bb < BATCH; bb++) acc[bb] = 0.f;

    #pragma unroll 4
    for (int dd = 0; dd < KLEN; dd++) {
        float wv = W[(long)(kc * KLEN + dd) * DIM + j];
        #pragma unroll
        for (int bb = 0; bb < BATCH; bb++)
            acc[bb] += s_in[bb][dd] * wv;
    }
    #pragma unroll
    for (int bb = 0; bb < BATCH; bb++)
        part[(kc * BATCH + bb) * DIM + j] = acc[bb];
}

// ---------------------------------------------------------------------------
// Kernel 7: reduce mlp2 partials + bias -> out.
// ---------------------------------------------------------------------------
__global__ __launch_bounds__(512) void mlp2_reduce_kernel(
    const float* __restrict__ bias, float* __restrict__ out)
{
    const int b = blockIdx.x;
    const int j = threadIdx.x;
    float s = 0.f;
    #pragma unroll
    for (int kc = 0; kc < KCHUNKS; kc++)
        s += g_p2[(kc * BATCH + b) * DIM + j];
    out[b * DIM + j] = s + bias[j];
}

// ---------------------------------------------------------------------------
extern "C" void kernel_launch(void* const* d_in, const int* in_sizes, int n_in,
                              void* d_out, int out_size)
{
    const float* x   = (const float*)d_in[0];
    const float* aW1 = (const float*)d_in[1];
    const float* ab1 = (const float*)d_in[2];
    const float* aW2 = (const float*)d_in[3];
    const float* ab2 = (const float*)d_in[4];
    const float* pW1 = (const float*)d_in[5];
    const float* pb1 = (const float*)d_in[6];
    const float* pW2 = (const float*)d_in[7];
    const float* pb2 = (const float*)d_in[8];

    float* out = (float*)d_out;
    float* proj    = out;                 // [B, DIM]
    float* weights = out + BATCH * DIM;   // [B, NINST]

    float* d_p1;  cudaGetSymbolAddress((void**)&d_p1, g_p1);
    float* d_p2;  cudaGetSymbolAddress((void**)&d_p2, g_p2);

    conv_w1_kernel<<<(DIM * HID + 255) / 256, 256>>>(aW1);
    attn_kernel<<<(BATCH * NINST) / BM, 256>>>(x, ab1, aW2, ab2, weights);
    select_kernel<<<BATCH, 512>>>(weights);
    refine_finalize_kernel<<<BATCH, 512>>>(x, aW1, ab1, aW2, ab2);
    gather_kernel<<<dim3(GCHUNKS, BATCH), 128>>>(x, weights);
    mlp1_part_kernel<<<dim3(DIM / 128, KCHUNKS), 128>>>(pW1, d_p1);
    mlp2_part_kernel<<<dim3(DIM / 128, KCHUNKS), 128>>>(pW2, pb1, d_p2);
    mlp2_reduce_kernel<<<BATCH, 512>>>(pb2, proj);
}

// round 10
// speedup vs baseline: 2.5349x; 2.5349x over previous
#include <cuda_runtime.h>
#include <cuda_fp16.h>
#include <math.h>
#include <stdint.h>

#define BATCH 8
#define NINST 8192
#define DIM   512
#define HID   64
#define TOPK_K 2457

#define GCHUNKS 64
#define GROWS   (NINST / GCHUNKS)   // 128

#define KCHUNKS 16
#define KLEN    (DIM / KCHUNKS)     // 32

// attn tiling
#define BM 128
#define BN 64
#define BK 32
#define NCH (DIM / BK)              // 16

#define CAP  512
#define BAND 4e-4f

// scratch (device globals; no allocation allowed)
__device__ __align__(16) __half g_w1h[DIM * HID];  // aW1 fp16, [k][n]
__device__ float    g_part[GCHUNKS * BATCH * DIM];
__device__ float    g_p1[KCHUNKS * BATCH * DIM];
__device__ float    g_p2[KCHUNKS * BATCH * DIM];
__device__ unsigned g_thr[BATCH];                 // approx kth weight (bits)
__device__ int      g_above[BATCH];               // #(w > thr+BAND)
__device__ int      g_ccnt[BATCH];                // candidate count
__device__ int      g_cand[BATCH][CAP];           // candidate indices
__device__ float    g_cval[BATCH][CAP];           // refined fp32 weights
__device__ unsigned char g_flag[BATCH * NINST];   // boundary-selected flags

__device__ __forceinline__ float gelu_f(float v) {
    float u = 0.7978845608028654f * (v + 0.044715f * v * v * v);
    return 0.5f * v * (1.0f + tanhf(u));
}

__device__ __forceinline__ void cp16(uint32_t sdst, const void* gsrc) {
    asm volatile("cp.async.cg.shared.global [%0], [%1], 16;" :: "r"(sdst), "l"(gsrc));
}

__device__ __forceinline__ void hmma(float* c, const unsigned* a, const unsigned* b) {
    asm volatile(
        "mma.sync.aligned.m16n8k16.row.col.f32.f16.f16.f32 "
        "{%0,%1,%2,%3}, {%4,%5,%6,%7}, {%8,%9}, {%0,%1,%2,%3};"
        : "+f"(c[0]), "+f"(c[1]), "+f"(c[2]), "+f"(c[3])
        : "r"(a[0]), "r"(a[1]), "r"(a[2]), "r"(a[3]), "r"(b[0]), "r"(b[1]));
}

__device__ __forceinline__ void ldm_x4(unsigned* r, uint32_t addr) {
    asm volatile("ldmatrix.sync.aligned.m8n8.x4.shared.b16 {%0,%1,%2,%3}, [%4];"
                 : "=r"(r[0]), "=r"(r[1]), "=r"(r[2]), "=r"(r[3]) : "r"(addr));
}
__device__ __forceinline__ void ldm_x4t(unsigned* r, uint32_t addr) {
    asm volatile("ldmatrix.sync.aligned.m8n8.x4.trans.shared.b16 {%0,%1,%2,%3}, [%4];"
                 : "=r"(r[0]), "=r"(r[1]), "=r"(r[2]), "=r"(r[3]) : "r"(addr));
}

// ---------------------------------------------------------------------------
// Kernel 0: round aW1 to fp16.
// ---------------------------------------------------------------------------
__global__ __launch_bounds__(256) void conv_w1_kernel(const float* __restrict__ aW1)
{
    int i = blockIdx.x * 256 + threadIdx.x;
    if (i < DIM * HID)
        g_w1h[i] = __float2half_rn(aW1[i]);
}

// ---------------------------------------------------------------------------
// Kernel 1: fused attention-score MLP, fp16 HMMA 2-term (A = hi+lo, B = fp16).
// (unchanged — validated at 5.1e-5)
// ---------------------------------------------------------------------------
__global__ __launch_bounds__(256) void attn_kernel(
    const float* __restrict__ x,
    const float* __restrict__ ab1,
    const float* __restrict__ aW2,
    const float* __restrict__ ab2,
    float* __restrict__ wout)
{
    __shared__ __align__(16) __half Ah[BM][40];
    __shared__ __align__(16) __half Al[BM][40];
    __shared__ __align__(16) __half Bh[2][BK][72];
    __shared__ float red[128][2];

    const int tid   = threadIdx.x;
    const int lane  = tid & 31;
    const int warp  = tid >> 5;
    const int warpM = warp >> 1;
    const int warpN = warp & 1;
    const long rowBase = (long)blockIdx.x * BM;
    const float* xb = x + rowBase * DIM;

    float acc[2][4][4];
    #pragma unroll
    for (int mi = 0; mi < 2; mi++)
        #pragma unroll
        for (int ni = 0; ni < 4; ni++)
            #pragma unroll
            for (int q = 0; q < 4; q++) acc[mi][ni][q] = 0.f;

    auto loadB = [&](int s, int c) {
        int r = tid >> 3, g = tid & 7;
        uint32_t dh = (uint32_t)__cvta_generic_to_shared(&Bh[s][r][g * 8]);
        cp16(dh, g_w1h + (c * BK + r) * HID + g * 8);
        asm volatile("cp.async.commit_group;");
    };

    const int ar = tid >> 1;
    const int ah = tid & 1;
    const float* xrow = xb + (long)ar * DIM + ah * 16;

    loadB(0, 0);
    float4 xr[4];
    #pragma unroll
    for (int q = 0; q < 4; q++)
        xr[q] = *reinterpret_cast<const float4*>(xrow + q * 4);

    for (int c = 0; c < NCH; c++) {
        unsigned hw[8], lw[8];
        const float* xv = reinterpret_cast<const float*>(xr);
        #pragma unroll
        for (int e = 0; e < 8; e++) {
            float v0 = xv[2 * e], v1 = xv[2 * e + 1];
            __half h0 = __float2half_rn(v0);
            __half l0 = __float2half_rn(v0 - __half2float(h0));
            __half h1 = __float2half_rn(v1);
            __half l1 = __float2half_rn(v1 - __half2float(h1));
            __half2 hp = __halves2half2(h0, h1);
            __half2 lp = __halves2half2(l0, l1);
            hw[e] = *reinterpret_cast<unsigned*>(&hp);
            lw[e] = *reinterpret_cast<unsigned*>(&lp);
        }
        float4 xn[4];
        if (c + 1 < NCH) {
            #pragma unroll
            for (int q = 0; q < 4; q++)
                xn[q] = *reinterpret_cast<const float4*>(xrow + (c + 1) * BK + q * 4);
        }
        __syncthreads();

        {
            char* pa = reinterpret_cast<char*>(&Ah[0][0]) + ar * 80 + ah * 32;
            char* pl = reinterpret_cast<char*>(&Al[0][0]) + ar * 80 + ah * 32;
            *reinterpret_cast<uint4*>(pa)      = make_uint4(hw[0], hw[1], hw[2], hw[3]);
            *reinterpret_cast<uint4*>(pa + 16) = make_uint4(hw[4], hw[5], hw[6], hw[7]);
            *reinterpret_cast<uint4*>(pl)      = make_uint4(lw[0], lw[1], lw[2], lw[3]);
            *reinterpret_cast<uint4*>(pl + 16) = make_uint4(lw[4], lw[5], lw[6], lw[7]);
        }
        if (c + 1 < NCH) {
            loadB((c + 1) & 1, c + 1);
            asm volatile("cp.async.wait_group 1;");
        } else {
            asm volatile("cp.async.wait_group 0;");
        }
        __syncthreads();

        const int st = c & 1;
        #pragma unroll
        for (int ks = 0; ks < 2; ks++) {
            const int k0 = ks * 16;
            unsigned Ahf[2][4], Alf[2][4];
            #pragma unroll
            for (int mi = 0; mi < 2; mi++) {
                int arow2 = warpM * 32 + mi * 16 + (lane & 15);
                int acol  = k0 + ((lane >> 4) << 3);
                uint32_t base = (uint32_t)__cvta_generic_to_shared(&Ah[arow2][acol]);
                ldm_x4(Ahf[mi], base);
                uint32_t basel = (uint32_t)__cvta_generic_to_shared(&Al[arow2][acol]);
                ldm_x4(Alf[mi], basel);
            }
            unsigned Bhf[4][2];
            #pragma unroll
            for (int pr = 0; pr < 2; pr++) {
                int brow = k0 + (lane & 15);
                int bcol = warpN * 32 + pr * 16 + ((lane >> 4) << 3);
                unsigned t4[4];
                uint32_t bb = (uint32_t)__cvta_generic_to_shared(&Bh[st][brow][bcol]);
                ldm_x4t(t4, bb);
                Bhf[pr * 2][0] = t4[0]; Bhf[pr * 2][1] = t4[1];
                Bhf[pr * 2 + 1][0] = t4[2]; Bhf[pr * 2 + 1][1] = t4[3];
            }
            #pragma unroll
            for (int mi = 0; mi < 2; mi++)
                #pragma unroll
                for (int ni = 0; ni < 4; ni++) {
                    hmma(acc[mi][ni], Ahf[mi], Bhf[ni]);
                    hmma(acc[mi][ni], Alf[mi], Bhf[ni]);
                }
        }
        #pragma unroll
        for (int q = 0; q < 4; q++) xr[q] = xn[q];
    }

    const int lk = lane & 3;
    const int lr = lane >> 2;
    float b1v[4][2], w2v[4][2];
    #pragma unroll
    for (int ni = 0; ni < 4; ni++) {
        int col = warpN * 32 + ni * 8 + 2 * lk;
        b1v[ni][0] = ab1[col];     b1v[ni][1] = ab1[col + 1];
        w2v[ni][0] = aW2[col];     w2v[ni][1] = aW2[col + 1];
    }
    float p[2][2] = {{0.f, 0.f}, {0.f, 0.f}};
    #pragma unroll
    for (int mi = 0; mi < 2; mi++)
        #pragma unroll
        for (int ni = 0; ni < 4; ni++) {
            p[mi][0] += gelu_f(acc[mi][ni][0] + b1v[ni][0]) * w2v[ni][0]
                      + gelu_f(acc[mi][ni][1] + b1v[ni][1]) * w2v[ni][1];
            p[mi][1] += gelu_f(acc[mi][ni][2] + b1v[ni][0]) * w2v[ni][0]
                      + gelu_f(acc[mi][ni][3] + b1v[ni][1]) * w2v[ni][1];
        }
    #pragma unroll
    for (int mi = 0; mi < 2; mi++)
        #pragma unroll
        for (int h = 0; h < 2; h++) {
            p[mi][h] += __shfl_xor_sync(0xffffffffu, p[mi][h], 1);
            p[mi][h] += __shfl_xor_sync(0xffffffffu, p[mi][h], 2);
        }
    if (lk == 0) {
        #pragma unroll
        for (int mi = 0; mi < 2; mi++) {
            int r = warpM * 32 + mi * 16 + lr;
            red[r][warpN]     = p[mi][0];
            red[r + 8][warpN] = p[mi][1];
        }
    }
    __syncthreads();
    if (tid < 128) {
        float s = red[tid][0] + red[tid][1] + ab2[0];
        wout[rowBase + tid] = 1.0f / (1.0f + expf(-s));
    }
}

// ---------------------------------------------------------------------------
// Kernel 2: radix-select kth value + band candidate collection + flag reset.
// ---------------------------------------------------------------------------
__global__ __launch_bounds__(512) void select_kernel(const float* __restrict__ w)
{
    __shared__ unsigned sv[NINST];
    __shared__ int hist[16][256];
    __shared__ unsigned s_prefix;
    __shared__ int s_k, s_above, s_cnt;

    const int b = blockIdx.x;
    const int tid = threadIdx.x;
    const int wid = tid >> 5;
    const float* wb = w + b * NINST;

    for (int i = tid; i < NINST; i += 512)
        sv[i] = __float_as_uint(wb[i]);
    if (tid == 0) { s_prefix = 0u; s_k = TOPK_K; s_above = 0; s_cnt = 0; }
    __syncthreads();

    for (int r = 0; r < 4; r++) {
        for (int i = tid; i < 16 * 256; i += 512)
            hist[i >> 8][i & 255] = 0;
        __syncthreads();
        const unsigned pref = s_prefix;
        const int sh = 24 - 8 * r;
        for (int i = tid; i < NINST; i += 512) {
            unsigned v = sv[i];
            bool ok = (r == 0) || ((v >> (sh + 8)) == pref);
            if (ok) atomicAdd(&hist[wid][(v >> sh) & 255], 1);
        }
        __syncthreads();
        if (tid < 256) {
            int s = hist[0][tid];
            #pragma unroll
            for (int h = 1; h < 16; h++) s += hist[h][tid];
            hist[0][tid] = s;
        }
        __syncthreads();
        if (tid == 0) {
            int k = s_k, cum = 0, bsel = 0;
            for (int bb = 255; bb >= 0; --bb) {
                cum += hist[0][bb];
                if (cum >= k) { bsel = bb; s_k = k - (cum - hist[0][bb]); break; }
            }
            s_prefix = (pref << 8) | (unsigned)bsel;
        }
        __syncthreads();
    }

    const float t   = __uint_as_float(s_prefix);
    const float thi = t + BAND;
    const float tlo = t - BAND;

    int la = 0;
    for (int i = tid; i < NINST; i += 512) {
        float wv = __uint_as_float(sv[i]);
        g_flag[b * NINST + i] = 0;
        if (wv > thi) la++;
        else if (wv >= tlo) {
            int p = atomicAdd(&s_cnt, 1);
            if (p < CAP) g_cand[b][p] = i;
        }
    }
    atomicAdd(&s_above, la);
    __syncthreads();
    if (tid == 0) {
        g_thr[b]   = s_prefix;
        g_above[b] = s_above;
        g_ccnt[b]  = s_cnt < CAP ? s_cnt : CAP;
    }
}

// ---------------------------------------------------------------------------
// Kernel 3: exact fp32 score recompute for band candidates.
// grid (32, BATCH), block 256; x row staged in smem (coalesced) first.
// (R8 version — measured 17 µs)
// ---------------------------------------------------------------------------
__global__ __launch_bounds__(256) void refine_kernel(
    const float* __restrict__ x,  const float* __restrict__ aW1,
    const float* __restrict__ ab1, const float* __restrict__ aW2,
    const float* __restrict__ ab2)
{
    const int b = blockIdx.y;
    const int cnt = g_ccnt[b];
    __shared__ float sx[DIM];
    __shared__ float sh4[4][64];
    __shared__ float sr[2];
    const int tid = threadIdx.x;
    const int q = tid >> 6;       // K quarter
    const int j = tid & 63;       // hidden unit

    for (int ci = blockIdx.x; ci < cnt; ci += 32) {
        const int idx = g_cand[b][ci];
        const float* xr = x + ((long)b * NINST + idx) * DIM;
        sx[tid]       = xr[tid];
        sx[tid + 256] = xr[tid + 256];
        __syncthreads();

        const float* wp = aW1 + (long)q * 128 * HID + j;
        const float* xq = sx + q * 128;
        float a0 = 0.f, a1 = 0.f;
        #pragma unroll
        for (int d = 0; d < 128; d += 2) {
            a0 += xq[d]     * wp[(long)d * HID];
            a1 += xq[d + 1] * wp[(long)(d + 1) * HID];
        }
        sh4[q][j] = a0 + a1;
        __syncthreads();

        if (tid < 64) {
            float hsum = sh4[0][j] + sh4[1][j] + sh4[2][j] + sh4[3][j];
            float hv = gelu_f(hsum + ab1[j]) * aW2[j];
            #pragma unroll
            for (int off = 16; off >= 1; off >>= 1)
                hv += __shfl_down_sync(0xffffffffu, hv, off);
            if ((j & 31) == 0) sr[j >> 5] = hv;
        }
        __syncthreads();
        if (tid == 0) {
            float logit = sr[0] + sr[1] + ab2[0];
            g_cval[b][ci] = 1.0f / (1.0f + expf(-logit));
        }
        __syncthreads();
    }
}

// ---------------------------------------------------------------------------
// Kernel 4: exact ranking among candidates -> flags (value desc, index asc).
// ---------------------------------------------------------------------------
__global__ __launch_bounds__(256) void finalize_kernel()
{
    __shared__ float v[CAP];
    __shared__ int  ix[CAP];
    const int b = blockIdx.x;
    const int tid = threadIdx.x;
    const int cnt  = g_ccnt[b];
    const int need = TOPK_K - g_above[b];

    for (int i = tid; i < cnt; i += 256) { v[i] = g_cval[b][i]; ix[i] = g_cand[b][i]; }
    __syncthreads();
    for (int i = tid; i < cnt; i += 256) {
        float vi = v[i]; int xi = ix[i];
        int rank = 0;
        for (int j = 0; j < cnt; j++)
            rank += (v[j] > vi) || (v[j] == vi && ix[j] < xi);
        if (rank < need) g_flag[b * NINST + xi] = 1;
    }
}

// ---------------------------------------------------------------------------
// Kernel 5: weighted gather-sum with per-block index compaction.
// (R9 version — kept, saved ~30 µs)
// ---------------------------------------------------------------------------
__global__ __launch_bounds__(128) void gather_kernel(
    const float* __restrict__ x, const float* __restrict__ w)
{
    __shared__ int   sel[GROWS];
    __shared__ float sw[GROWS];
    __shared__ int   wbase[4];
    __shared__ int   scount;

    const int b  = blockIdx.y;
    const int rc = blockIdx.x;
    const int r0 = rc * GROWS;
    const int tid = threadIdx.x;
    const int lane = tid & 31;
    const int wrp = tid >> 5;

    const float thi = __uint_as_float(g_thr[b]) + BAND;

    float wi = w[b * NINST + r0 + tid];
    bool pick = (wi > thi) || g_flag[b * NINST + r0 + tid];
    unsigned mask = __ballot_sync(0xffffffffu, pick);
    int wcnt = __popc(mask);
    if (lane == 0) wbase[wrp] = wcnt;
    __syncthreads();
    if (tid == 0) {
        int s = 0;
        #pragma unroll
        for (int q = 0; q < 4; q++) { int c = wbase[q]; wbase[q] = s; s += c; }
        scount = s;
    }
    __syncthreads();
    if (pick) {
        int pos = wbase[wrp] + __popc(mask & ((1u << lane) - 1u));
        sel[pos] = tid;
        sw[pos]  = wi;
    }
    __syncthreads();

    const int d4 = tid * 4;
    const int nsel = scount;
    const float* xb = x + ((long)b * NINST + r0) * DIM + d4;

    float4 acc = make_float4(0.f, 0.f, 0.f, 0.f);
    for (int s = 0; s < nsel; s++) {
        float ws = sw[s];
        float4 xv = *reinterpret_cast<const float4*>(xb + (long)sel[s] * DIM);
        acc.x += ws * xv.x; acc.y += ws * xv.y;
        acc.z += ws * xv.z; acc.w += ws * xv.w;
    }
    *reinterpret_cast<float4*>(&g_part[(rc * BATCH + b) * DIM + d4]) = acc;
}

// ---------------------------------------------------------------------------
// Kernel 6: mlp1 split-K partials with inline emb reduction.
// ---------------------------------------------------------------------------
__global__ __launch_bounds__(128) void mlp1_part_kernel(
    const float* __restrict__ W, float* __restrict__ part)
{
    __shared__ float s_in[BATCH][KLEN];
    const int kc = blockIdx.y;
    const int j  = blockIdx.x * 128 + threadIdx.x;

    #pragma unroll
    for (int it = 0; it < (BATCH * KLEN) / 128; it++) {
        int i = it * 128 + threadIdx.x;
        int bb = i / KLEN, dd = i % KLEN;
        const float* p = g_part + bb * DIM + kc * KLEN + dd;
        float s0 = 0.f, s1 = 0.f;
        #pragma unroll
        for (int rc = 0; rc < GCHUNKS; rc += 2) {
            s0 += p[(long)rc * BATCH * DIM];
            s1 += p[(long)(rc + 1) * BATCH * DIM];
        }
        s_in[bb][dd] = (s0 + s1) * (1.0f / (float)TOPK_K);
    }
    __syncthreads();

    float acc[BATCH];
    #pragma unroll
    for (int bb = 0; bb < BATCH; bb++) acc[bb] = 0.f;

    #pragma unroll 4
    for (int dd = 0; dd < KLEN; dd++) {
        float wv = W[(long)(kc * KLEN + dd) * DIM + j];
        #pragma unroll
        for (int bb = 0; bb < BATCH; bb++)
            acc[bb] += s_in[bb][dd] * wv;
    }
    #pragma unroll
    for (int bb = 0; bb < BATCH; bb++)
        part[(kc * BATCH + bb) * DIM + j] = acc[bb];
}

// ---------------------------------------------------------------------------
// Kernel 7: mlp2 split-K partials with inline (reduce p1 + bias + gelu).
// ---------------------------------------------------------------------------
__global__ __launch_bounds__(128) void mlp2_part_kernel(
    const float* __restrict__ W, const float* __restrict__ b1,
    float* __restrict__ part)
{
    __shared__ float s_in[BATCH][KLEN];
    const int kc = blockIdx.y;
    const int j  = blockIdx.x * 128 + threadIdx.x;

    #pragma unroll
    for (int it = 0; it < (BATCH * KLEN) / 128; it++) {
        int i = it * 128 + threadIdx.x;
        int bb = i / KLEN, dd = i % KLEN;
        const float* p = g_p1 + bb * DIM + kc * KLEN + dd;
        float s = 0.f;
        #pragma unroll
        for (int c = 0; c < KCHUNKS; c++)
            s += p[(long)c * BATCH * DIM];
        s_in[bb][dd] = gelu_f(s + b1[kc * KLEN + dd]);
    }
    __syncthreads();

    float acc[BATCH];
    #pragma unroll
    for (int bb = 0; bb < BATCH; bb++) acc[bb] = 0.f;

    #pragma unroll 4
    for (int dd = 0; dd < KLEN; dd++) {
        float wv = W[(long)(kc * KLEN + dd) * DIM + j];
        #pragma unroll
        for (int bb = 0; bb < BATCH; bb++)
            acc[bb] += s_in[bb][dd] * wv;
    }
    #pragma unroll
    for (int bb = 0; bb < BATCH; bb++)
        part[(kc * BATCH + bb) * DIM + j] = acc[bb];
}

// ---------------------------------------------------------------------------
// Kernel 8: reduce mlp2 partials + bias -> out.
// ---------------------------------------------------------------------------
__global__ __launch_bounds__(512) void mlp2_reduce_kernel(
    const float* __restrict__ bias, float* __restrict__ out)
{
    const int b = blockIdx.x;
    const int j = threadIdx.x;
    float s = 0.f;
    #pragma unroll
    for (int kc = 0; kc < KCHUNKS; kc++)
        s += g_p2[(kc * BATCH + b) * DIM + j];
    out[b * DIM + j] = s + bias[j];
}

// ---------------------------------------------------------------------------
extern "C" void kernel_launch(void* const* d_in, const int* in_sizes, int n_in,
                              void* d_out, int out_size)
{
    const float* x   = (const float*)d_in[0];
    const float* aW1 = (const float*)d_in[1];
    const float* ab1 = (const float*)d_in[2];
    const float* aW2 = (const float*)d_in[3];
    const float* ab2 = (const float*)d_in[4];
    const float* pW1 = (const float*)d_in[5];
    const float* pb1 = (const float*)d_in[6];
    const float* pW2 = (const float*)d_in[7];
    const float* pb2 = (const float*)d_in[8];

    float* out = (float*)d_out;
    float* proj    = out;                 // [B, DIM]
    float* weights = out + BATCH * DIM;   // [B, NINST]

    float* d_p1;  cudaGetSymbolAddress((void**)&d_p1, g_p1);
    float* d_p2;  cudaGetSymbolAddress((void**)&d_p2, g_p2);

    conv_w1_kernel<<<(DIM * HID + 255) / 256, 256>>>(aW1);
    attn_kernel<<<(BATCH * NINST) / BM, 256>>>(x, ab1, aW2, ab2, weights);
    select_kernel<<<BATCH, 512>>>(weights);
    refine_kernel<<<dim3(32, BATCH), 256>>>(x, aW1, ab1, aW2, ab2);
    finalize_kernel<<<BATCH, 256>>>();
    gather_kernel<<<dim3(GCHUNKS, BATCH), 128>>>(x, weights);
    mlp1_part_kernel<<<dim3(DIM / 128, KCHUNKS), 128>>>(pW1, d_p1);
    mlp2_part_kernel<<<dim3(DIM / 128, KCHUNKS), 128>>>(pW2, pb1, d_p2);
    mlp2_reduce_kernel<<<BATCH, 512>>>(pb2, proj);
}

// round 11
// speedup vs baseline: 2.6651x; 1.0514x over previous
#include <cuda_runtime.h>
#include <cuda_fp16.h>
#include <math.h>
#include <stdint.h>

#define BATCH 8
#define NINST 8192
#define DIM   512
#define HID   64
#define TOPK_K 2457

#define GCHUNKS 64
#define GROWS   (NINST / GCHUNKS)   // 128

#define KCHUNKS 16
#define KLEN    (DIM / KCHUNKS)     // 32

// attn tiling
#define BM 128
#define BN 64
#define BK 32
#define NCH (DIM / BK)              // 16

#define CAP  512
#define BAND 1e-3f

// scratch (device globals; no allocation allowed)
__device__ __align__(16) __half g_w1h[DIM * HID];  // aW1 fp16, [k][n]
__device__ float    g_part[GCHUNKS * BATCH * DIM];
__device__ float    g_p1[KCHUNKS * BATCH * DIM];
__device__ float    g_p2[KCHUNKS * BATCH * DIM];
__device__ unsigned g_thr[BATCH];                 // approx kth weight (bits)
__device__ int      g_above[BATCH];               // #(w > thr+BAND)
__device__ int      g_ccnt[BATCH];                // candidate count
__device__ int      g_cand[BATCH][CAP];           // candidate indices
__device__ float    g_cval[BATCH][CAP];           // refined fp32 weights
__device__ unsigned char g_flag[BATCH * NINST];   // boundary-selected flags

__device__ __forceinline__ float gelu_f(float v) {
    float u = 0.7978845608028654f * (v + 0.044715f * v * v * v);
    return 0.5f * v * (1.0f + tanhf(u));
}

__device__ __forceinline__ void cp16(uint32_t sdst, const void* gsrc) {
    asm volatile("cp.async.cg.shared.global [%0], [%1], 16;" :: "r"(sdst), "l"(gsrc));
}

__device__ __forceinline__ void hmma(float* c, const unsigned* a, const unsigned* b) {
    asm volatile(
        "mma.sync.aligned.m16n8k16.row.col.f32.f16.f16.f32 "
        "{%0,%1,%2,%3}, {%4,%5,%6,%7}, {%8,%9}, {%0,%1,%2,%3};"
        : "+f"(c[0]), "+f"(c[1]), "+f"(c[2]), "+f"(c[3])
        : "r"(a[0]), "r"(a[1]), "r"(a[2]), "r"(a[3]), "r"(b[0]), "r"(b[1]));
}

__device__ __forceinline__ void ldm_x4(unsigned* r, uint32_t addr) {
    asm volatile("ldmatrix.sync.aligned.m8n8.x4.shared.b16 {%0,%1,%2,%3}, [%4];"
                 : "=r"(r[0]), "=r"(r[1]), "=r"(r[2]), "=r"(r[3]) : "r"(addr));
}
__device__ __forceinline__ void ldm_x4t(unsigned* r, uint32_t addr) {
    asm volatile("ldmatrix.sync.aligned.m8n8.x4.trans.shared.b16 {%0,%1,%2,%3}, [%4];"
                 : "=r"(r[0]), "=r"(r[1]), "=r"(r[2]), "=r"(r[3]) : "r"(addr));
}

// ---------------------------------------------------------------------------
// Kernel 0: round aW1 to fp16.
// ---------------------------------------------------------------------------
__global__ __launch_bounds__(256) void conv_w1_kernel(const float* __restrict__ aW1)
{
    int i = blockIdx.x * 256 + threadIdx.x;
    if (i < DIM * HID)
        g_w1h[i] = __float2half_rn(aW1[i]);
}

// ---------------------------------------------------------------------------
// Kernel 1: fused attention-score MLP, plain fp16 HMMA (selection armored by
// the exact refine pass; weights output err ~2e-4 rel, within 1e-3).
// Block: 128 rows x 64 hid, 256 threads = 8 warps (4M x 2N), warp tile 32x32.
// ---------------------------------------------------------------------------
__global__ __launch_bounds__(256) void attn_kernel(
    const float* __restrict__ x,
    const float* __restrict__ ab1,
    const float* __restrict__ aW2,
    const float* __restrict__ ab2,
    float* __restrict__ wout)
{
    __shared__ __align__(16) __half Ah[BM][40];
    __shared__ __align__(16) __half Bh[2][BK][72];
    __shared__ float red[128][2];

    const int tid   = threadIdx.x;
    const int lane  = tid & 31;
    const int warp  = tid >> 5;
    const int warpM = warp >> 1;
    const int warpN = warp & 1;
    const long rowBase = (long)blockIdx.x * BM;
    const float* xb = x + rowBase * DIM;

    float acc[2][4][4];
    #pragma unroll
    for (int mi = 0; mi < 2; mi++)
        #pragma unroll
        for (int ni = 0; ni < 4; ni++)
            #pragma unroll
            for (int q = 0; q < 4; q++) acc[mi][ni][q] = 0.f;

    auto loadB = [&](int s, int c) {
        int r = tid >> 3, g = tid & 7;
        uint32_t dh = (uint32_t)__cvta_generic_to_shared(&Bh[s][r][g * 8]);
        cp16(dh, g_w1h + (c * BK + r) * HID + g * 8);
        asm volatile("cp.async.commit_group;");
    };

    const int ar = tid >> 1;
    const int ah = tid & 1;
    const float* xrow = xb + (long)ar * DIM + ah * 16;

    loadB(0, 0);
    float4 xr[4];
    #pragma unroll
    for (int q = 0; q < 4; q++)
        xr[q] = *reinterpret_cast<const float4*>(xrow + q * 4);

    for (int c = 0; c < NCH; c++) {
        // convert 16 floats -> 8 packed half2 (single cvt per pair)
        unsigned hw[8];
        const float* xv = reinterpret_cast<const float*>(xr);
        #pragma unroll
        for (int e = 0; e < 8; e++) {
            __half2 hp = __float22half2_rn(make_float2(xv[2 * e], xv[2 * e + 1]));
            hw[e] = *reinterpret_cast<unsigned*>(&hp);
        }
        float4 xn[4];
        if (c + 1 < NCH) {
            #pragma unroll
            for (int q = 0; q < 4; q++)
                xn[q] = *reinterpret_cast<const float4*>(xrow + (c + 1) * BK + q * 4);
        }
        __syncthreads();   // prior iteration's ldmatrix reads complete

        {
            char* pa = reinterpret_cast<char*>(&Ah[0][0]) + ar * 80 + ah * 32;
            *reinterpret_cast<uint4*>(pa)      = make_uint4(hw[0], hw[1], hw[2], hw[3]);
            *reinterpret_cast<uint4*>(pa + 16) = make_uint4(hw[4], hw[5], hw[6], hw[7]);
        }
        if (c + 1 < NCH) {
            loadB((c + 1) & 1, c + 1);
            asm volatile("cp.async.wait_group 1;");
        } else {
            asm volatile("cp.async.wait_group 0;");
        }
        __syncthreads();

        const int st = c & 1;
        #pragma unroll
        for (int ks = 0; ks < 2; ks++) {
            const int k0 = ks * 16;
            unsigned Ahf[2][4];
            #pragma unroll
            for (int mi = 0; mi < 2; mi++) {
                int arow2 = warpM * 32 + mi * 16 + (lane & 15);
                int acol  = k0 + ((lane >> 4) << 3);
                uint32_t base = (uint32_t)__cvta_generic_to_shared(&Ah[arow2][acol]);
                ldm_x4(Ahf[mi], base);
            }
            unsigned Bhf[4][2];
            #pragma unroll
            for (int pr = 0; pr < 2; pr++) {
                int brow = k0 + (lane & 15);
                int bcol = warpN * 32 + pr * 16 + ((lane >> 4) << 3);
                unsigned t4[4];
                uint32_t bb = (uint32_t)__cvta_generic_to_shared(&Bh[st][brow][bcol]);
                ldm_x4t(t4, bb);
                Bhf[pr * 2][0] = t4[0]; Bhf[pr * 2][1] = t4[1];
                Bhf[pr * 2 + 1][0] = t4[2]; Bhf[pr * 2 + 1][1] = t4[3];
            }
            #pragma unroll
            for (int mi = 0; mi < 2; mi++)
                #pragma unroll
                for (int ni = 0; ni < 4; ni++)
                    hmma(acc[mi][ni], Ahf[mi], Bhf[ni]);
        }
        #pragma unroll
        for (int q = 0; q < 4; q++) xr[q] = xn[q];
    }

    const int lk = lane & 3;
    const int lr = lane >> 2;
    float b1v[4][2], w2v[4][2];
    #pragma unroll
    for (int ni = 0; ni < 4; ni++) {
        int col = warpN * 32 + ni * 8 + 2 * lk;
        b1v[ni][0] = ab1[col];     b1v[ni][1] = ab1[col + 1];
        w2v[ni][0] = aW2[col];     w2v[ni][1] = aW2[col + 1];
    }
    float p[2][2] = {{0.f, 0.f}, {0.f, 0.f}};
    #pragma unroll
    for (int mi = 0; mi < 2; mi++)
        #pragma unroll
        for (int ni = 0; ni < 4; ni++) {
            p[mi][0] += gelu_f(acc[mi][ni][0] + b1v[ni][0]) * w2v[ni][0]
                      + gelu_f(acc[mi][ni][1] + b1v[ni][1]) * w2v[ni][1];
            p[mi][1] += gelu_f(acc[mi][ni][2] + b1v[ni][0]) * w2v[ni][0]
                      + gelu_f(acc[mi][ni][3] + b1v[ni][1]) * w2v[ni][1];
        }
    #pragma unroll
    for (int mi = 0; mi < 2; mi++)
        #pragma unroll
        for (int h = 0; h < 2; h++) {
            p[mi][h] += __shfl_xor_sync(0xffffffffu, p[mi][h], 1);
            p[mi][h] += __shfl_xor_sync(0xffffffffu, p[mi][h], 2);
        }
    if (lk == 0) {
        #pragma unroll
        for (int mi = 0; mi < 2; mi++) {
            int r = warpM * 32 + mi * 16 + lr;
            red[r][warpN]     = p[mi][0];
            red[r + 8][warpN] = p[mi][1];
        }
    }
    __syncthreads();
    if (tid < 128) {
        float s = red[tid][0] + red[tid][1] + ab2[0];
        wout[rowBase + tid] = 1.0f / (1.0f + expf(-s));
    }
}

// ---------------------------------------------------------------------------
// Kernel 2: radix-select kth value + band candidate collection + flag reset.
// ---------------------------------------------------------------------------
__global__ __launch_bounds__(512) void select_kernel(const float* __restrict__ w)
{
    __shared__ unsigned sv[NINST];
    __shared__ int hist[16][256];
    __shared__ unsigned s_prefix;
    __shared__ int s_k, s_above, s_cnt;

    const int b = blockIdx.x;
    const int tid = threadIdx.x;
    const int wid = tid >> 5;
    const float* wb = w + b * NINST;

    for (int i = tid; i < NINST; i += 512)
        sv[i] = __float_as_uint(wb[i]);
    if (tid == 0) { s_prefix = 0u; s_k = TOPK_K; s_above = 0; s_cnt = 0; }
    __syncthreads();

    for (int r = 0; r < 4; r++) {
        for (int i = tid; i < 16 * 256; i += 512)
            hist[i >> 8][i & 255] = 0;
        __syncthreads();
        const unsigned pref = s_prefix;
        const int sh = 24 - 8 * r;
        for (int i = tid; i < NINST; i += 512) {
            unsigned v = sv[i];
            bool ok = (r == 0) || ((v >> (sh + 8)) == pref);
            if (ok) atomicAdd(&hist[wid][(v >> sh) & 255], 1);
        }
        __syncthreads();
        if (tid < 256) {
            int s = hist[0][tid];
            #pragma unroll
            for (int h = 1; h < 16; h++) s += hist[h][tid];
            hist[0][tid] = s;
        }
        __syncthreads();
        if (tid == 0) {
            int k = s_k, cum = 0, bsel = 0;
            for (int bb = 255; bb >= 0; --bb) {
                cum += hist[0][bb];
                if (cum >= k) { bsel = bb; s_k = k - (cum - hist[0][bb]); break; }
            }
            s_prefix = (pref << 8) | (unsigned)bsel;
        }
        __syncthreads();
    }

    const float t   = __uint_as_float(s_prefix);
    const float thi = t + BAND;
    const float tlo = t - BAND;

    int la = 0;
    for (int i = tid; i < NINST; i += 512) {
        float wv = __uint_as_float(sv[i]);
        g_flag[b * NINST + i] = 0;
        if (wv > thi) la++;
        else if (wv >= tlo) {
            int p = atomicAdd(&s_cnt, 1);
            if (p < CAP) g_cand[b][p] = i;
        }
    }
    atomicAdd(&s_above, la);
    __syncthreads();
    if (tid == 0) {
        g_thr[b]   = s_prefix;
        g_above[b] = s_above;
        g_ccnt[b]  = s_cnt < CAP ? s_cnt : CAP;
    }
}

// ---------------------------------------------------------------------------
// Kernel 3: exact fp32 score recompute for band candidates.
// grid (64, BATCH), block 256; x row staged in smem; aW1 loads in explicit
// 16-wide batches for MLP (fix for the regs=32 load-serialization).
// ---------------------------------------------------------------------------
__global__ __launch_bounds__(256) void refine_kernel(
    const float* __restrict__ x,  const float* __restrict__ aW1,
    const float* __restrict__ ab1, const float* __restrict__ aW2,
    const float* __restrict__ ab2)
{
    const int b = blockIdx.y;
    const int cnt = g_ccnt[b];
    __shared__ float sx[DIM];
    __shared__ float sh4[4][64];
    __shared__ float sr[2];
    const int tid = threadIdx.x;
    const int q = tid >> 6;       // K quarter
    const int j = tid & 63;       // hidden unit

    for (int ci = blockIdx.x; ci < cnt; ci += 64) {
        const int idx = g_cand[b][ci];
        const float* xr = x + ((long)b * NINST + idx) * DIM;
        sx[tid]       = xr[tid];
        sx[tid + 256] = xr[tid + 256];
        __syncthreads();

        const float* wp = aW1 + (long)(q * 128) * HID + j;
        const float* xq = sx + q * 128;
        float acc = 0.f;
        #pragma unroll
        for (int g0 = 0; g0 < 128; g0 += 16) {
            float wv[16];
            #pragma unroll
            for (int t = 0; t < 16; t++)
                wv[t] = wp[(long)(g0 + t) * HID];
            #pragma unroll
            for (int t = 0; t < 16; t++)
                acc += xq[g0 + t] * wv[t];
        }
        sh4[q][j] = acc;
        __syncthreads();

        if (tid < 64) {
            float hsum = sh4[0][j] + sh4[1][j] + sh4[2][j] + sh4[3][j];
            float hv = gelu_f(hsum + ab1[j]) * aW2[j];
            #pragma unroll
            for (int off = 16; off >= 1; off >>= 1)
                hv += __shfl_down_sync(0xffffffffu, hv, off);
            if ((j & 31) == 0) sr[j >> 5] = hv;
        }
        __syncthreads();
        if (tid == 0) {
            float logit = sr[0] + sr[1] + ab2[0];
            g_cval[b][ci] = 1.0f / (1.0f + expf(-logit));
        }
        __syncthreads();
    }
}

// ---------------------------------------------------------------------------
// Kernel 4: exact ranking among candidates -> flags (value desc, index asc).
// ---------------------------------------------------------------------------
__global__ __launch_bounds__(256) void finalize_kernel()
{
    __shared__ float v[CAP];
    __shared__ int  ix[CAP];
    const int b = blockIdx.x;
    const int tid = threadIdx.x;
    const int cnt  = g_ccnt[b];
    const int need = TOPK_K - g_above[b];

    for (int i = tid; i < cnt; i += 256) { v[i] = g_cval[b][i]; ix[i] = g_cand[b][i]; }
    __syncthreads();
    for (int i = tid; i < cnt; i += 256) {
        float vi = v[i]; int xi = ix[i];
        int rank = 0;
        for (int j = 0; j < cnt; j++)
            rank += (v[j] > vi) || (v[j] == vi && ix[j] < xi);
        if (rank < need) g_flag[b * NINST + xi] = 1;
    }
}

// ---------------------------------------------------------------------------
// Kernel 5: weighted gather-sum with per-block index compaction.
// ---------------------------------------------------------------------------
__global__ __launch_bounds__(128) void gather_kernel(
    const float* __restrict__ x, const float* __restrict__ w)
{
    __shared__ int   sel[GROWS];
    __shared__ float sw[GROWS];
    __shared__ int   wbase[4];
    __shared__ int   scount;

    const int b  = blockIdx.y;
    const int rc = blockIdx.x;
    const int r0 = rc * GROWS;
    const int tid = threadIdx.x;
    const int lane = tid & 31;
    const int wrp = tid >> 5;

    const float thi = __uint_as_float(g_thr[b]) + BAND;

    float wi = w[b * NINST + r0 + tid];
    bool pick = (wi > thi) || g_flag[b * NINST + r0 + tid];
    unsigned mask = __ballot_sync(0xffffffffu, pick);
    int wcnt = __popc(mask);
    if (lane == 0) wbase[wrp] = wcnt;
    __syncthreads();
    if (tid == 0) {
        int s = 0;
        #pragma unroll
        for (int q = 0; q < 4; q++) { int c = wbase[q]; wbase[q] = s; s += c; }
        scount = s;
    }
    __syncthreads();
    if (pick) {
        int pos = wbase[wrp] + __popc(mask & ((1u << lane) - 1u));
        sel[pos] = tid;
        sw[pos]  = wi;
    }
    __syncthreads();

    const int d4 = tid * 4;
    const int nsel = scount;
    const float* xb = x + ((long)b * NINST + r0) * DIM + d4;

    float4 acc = make_float4(0.f, 0.f, 0.f, 0.f);
    for (int s = 0; s < nsel; s++) {
        float ws = sw[s];
        float4 xv = *reinterpret_cast<const float4*>(xb + (long)sel[s] * DIM);
        acc.x += ws * xv.x; acc.y += ws * xv.y;
        acc.z += ws * xv.z; acc.w += ws * xv.w;
    }
    *reinterpret_cast<float4*>(&g_part[(rc * BATCH + b) * DIM + d4]) = acc;
}

// ---------------------------------------------------------------------------
// Kernel 6: mlp1 split-K partials with inline emb reduction.
// ---------------------------------------------------------------------------
__global__ __launch_bounds__(128) void mlp1_part_kernel(
    const float* __restrict__ W, float* __restrict__ part)
{
    __shared__ float s_in[BATCH][KLEN];
    const int kc = blockIdx.y;
    const int j  = blockIdx.x * 128 + threadIdx.x;

    #pragma unroll
    for (int it = 0; it < (BATCH * KLEN) / 128; it++) {
        int i = it * 128 + threadIdx.x;
        int bb = i / KLEN, dd = i % KLEN;
        const float* p = g_part + bb * DIM + kc * KLEN + dd;
        float s0 = 0.f, s1 = 0.f;
        #pragma unroll
        for (int rc = 0; rc < GCHUNKS; rc += 2) {
            s0 += p[(long)rc * BATCH * DIM];
            s1 += p[(long)(rc + 1) * BATCH * DIM];
        }
        s_in[bb][dd] = (s0 + s1) * (1.0f / (float)TOPK_K);
    }
    __syncthreads();

    float acc[BATCH];
    #pragma unroll
    for (int bb = 0; bb < BATCH; bb++) acc[bb] = 0.f;

    #pragma unroll 4
    for (int dd = 0; dd < KLEN; dd++) {
        float wv = W[(long)(kc * KLEN + dd) * DIM + j];
        #pragma unroll
        for (int bb = 0; bb < BATCH; bb++)
            acc[bb] += s_in[bb][dd] * wv;
    }
    #pragma unroll
    for (int bb = 0; bb < BATCH; bb++)
        part[(kc * BATCH + bb) * DIM + j] = acc[bb];
}

// ---------------------------------------------------------------------------
// Kernel 7: mlp2 split-K partials with inline (reduce p1 + bias + gelu).
// ---------------------------------------------------------------------------
__global__ __launch_bounds__(128) void mlp2_part_kernel(
    const float* __restrict__ W, const float* __restrict__ b1,
    float* __restrict__ part)
{
    __shared__ float s_in[BATCH][KLEN];
    const int kc = blockIdx.y;
    const int j  = blockIdx.x * 128 + threadIdx.x;

    #pragma unroll
    for (int it = 0; it < (BATCH * KLEN) / 128; it++) {
        int i = it * 128 + threadIdx.x;
        int bb = i / KLEN, dd = i % KLEN;
        const float* p = g_p1 + bb * DIM + kc * KLEN + dd;
        float s = 0.f;
        #pragma unroll
        for (int c = 0; c < KCHUNKS; c++)
            s += p[(long)c * BATCH * DIM];
        s_in[bb][dd] = gelu_f(s + b1[kc * KLEN + dd]);
    }
    __syncthreads();

    float acc[BATCH];
    #pragma unroll
    for (int bb = 0; bb < BATCH; bb++) acc[bb] = 0.f;

    #pragma unroll 4
    for (int dd = 0; dd < KLEN; dd++) {
        float wv = W[(long)(kc * KLEN + dd) * DIM + j];
        #pragma unroll
        for (int bb = 0; bb < BATCH; bb++)
            acc[bb] += s_in[bb][dd] * wv;
    }
    #pragma unroll
    for (int bb = 0; bb < BATCH; bb++)
        part[(kc * BATCH + bb) * DIM + j] = acc[bb];
}

// ---------------------------------------------------------------------------
// Kernel 8: reduce mlp2 partials + bias -> out.
// ---------------------------------------------------------------------------
__global__ __launch_bounds__(512) void mlp2_reduce_kernel(
    const float* __restrict__ bias, float* __restrict__ out)
{
    const int b = blockIdx.x;
    const int j = threadIdx.x;
    float s = 0.f;
    #pragma unroll
    for (int kc = 0; kc < KCHUNKS; kc++)
        s += g_p2[(kc * BATCH + b) * DIM + j];
    out[b * DIM + j] = s + bias[j];
}

// ---------------------------------------------------------------------------
extern "C" void kernel_launch(void* const* d_in, const int* in_sizes, int n_in,
                              void* d_out, int out_size)
{
    const float* x   = (const float*)d_in[0];
    const float* aW1 = (const float*)d_in[1];
    const float* ab1 = (const float*)d_in[2];
    const float* aW2 = (const float*)d_in[3];
    const float* ab2 = (const float*)d_in[4];
    const float* pW1 = (const float*)d_in[5];
    const float* pb1 = (const float*)d_in[6];
    const float* pW2 = (const float*)d_in[7];
    const float* pb2 = (const float*)d_in[8];

    float* out = (float*)d_out;
    float* proj    = out;                 // [B, DIM]
    float* weights = out + BATCH * DIM;   // [B, NINST]

    float* d_p1;  cudaGetSymbolAddress((void**)&d_p1, g_p1);
    float* d_p2;  cudaGetSymbolAddress((void**)&d_p2, g_p2);

    conv_w1_kernel<<<(DIM * HID + 255) / 256, 256>>>(aW1);
    attn_kernel<<<(BATCH * NINST) / BM, 256>>>(x, ab1, aW2, ab2, weights);
    select_kernel<<<BATCH, 512>>>(weights);
    refine_kernel<<<dim3(64, BATCH), 256>>>(x, aW1, ab1, aW2, ab2);
    finalize_kernel<<<BATCH, 256>>>();
    gather_kernel<<<dim3(GCHUNKS, BATCH), 128>>>(x, weights);
    mlp1_part_kernel<<<dim3(DIM / 128, KCHUNKS), 128>>>(pW1, d_p1);
    mlp2_part_kernel<<<dim3(DIM / 128, KCHUNKS), 128>>>(pW2, pb1, d_p2);
    mlp2_reduce_kernel<<<BATCH, 512>>>(pb2, proj);
}

// round 13
// speedup vs baseline: 3.2109x; 1.2048x over previous
#include <cuda_runtime.h>
#include <cuda_fp16.h>
#include <math.h>
#include <stdint.h>

#define BATCH 8
#define NINST 8192
#define DIM   512
#define HID   64
#define TOPK_K 2457

#define GCHUNKS 64
#define GROWS   (NINST / GCHUNKS)   // 128

#define KCHUNKS 16
#define KLEN    (DIM / KCHUNKS)     // 32

// attn tiling
#define BM 128
#define BN 64
#define BK 32
#define NCH (DIM / BK)              // 16

#define CAP  512
#define BAND 1e-3f

// scratch (device globals; no allocation allowed)
__device__ __align__(16) __half g_w1h[DIM * HID];  // aW1 fp16, [k][n]
__device__ float    g_part[GCHUNKS * BATCH * DIM];
__device__ float    g_p1[KCHUNKS * BATCH * DIM];
__device__ float    g_p2[KCHUNKS * BATCH * DIM];
__device__ unsigned g_thr[BATCH];                 // approx kth weight (bits)
__device__ int      g_above[BATCH];               // #(w > thr+BAND)
__device__ int      g_ccnt[BATCH];                // candidate count
__device__ int      g_cand[BATCH][CAP];           // candidate indices
__device__ float    g_cval[BATCH][CAP];           // refined fp32 weights
__device__ unsigned char g_flag[BATCH * NINST];   // boundary-selected flags

__device__ __forceinline__ float gelu_f(float v) {
    float u = 0.7978845608028654f * (v + 0.044715f * v * v * v);
    return 0.5f * v * (1.0f + tanhf(u));
}

__device__ __forceinline__ void cp16(uint32_t sdst, const void* gsrc) {
    asm volatile("cp.async.cg.shared.global [%0], [%1], 16;" :: "r"(sdst), "l"(gsrc));
}

__device__ __forceinline__ void hmma(float* c, const unsigned* a, const unsigned* b) {
    asm volatile(
        "mma.sync.aligned.m16n8k16.row.col.f32.f16.f16.f32 "
        "{%0,%1,%2,%3}, {%4,%5,%6,%7}, {%8,%9}, {%0,%1,%2,%3};"
        : "+f"(c[0]), "+f"(c[1]), "+f"(c[2]), "+f"(c[3])
        : "r"(a[0]), "r"(a[1]), "r"(a[2]), "r"(a[3]), "r"(b[0]), "r"(b[1]));
}

__device__ __forceinline__ void ldm_x4(unsigned* r, uint32_t addr) {
    asm volatile("ldmatrix.sync.aligned.m8n8.x4.shared.b16 {%0,%1,%2,%3}, [%4];"
                 : "=r"(r[0]), "=r"(r[1]), "=r"(r[2]), "=r"(r[3]) : "r"(addr));
}
__device__ __forceinline__ void ldm_x4t(unsigned* r, uint32_t addr) {
    asm volatile("ldmatrix.sync.aligned.m8n8.x4.trans.shared.b16 {%0,%1,%2,%3}, [%4];"
                 : "=r"(r[0]), "=r"(r[1]), "=r"(r[2]), "=r"(r[3]) : "r"(addr));
}

// ---------------------------------------------------------------------------
// Kernel 0: round aW1 to fp16.
// ---------------------------------------------------------------------------
__global__ __launch_bounds__(256) void conv_w1_kernel(const float* __restrict__ aW1)
{
    int i = blockIdx.x * 256 + threadIdx.x;
    if (i < DIM * HID)
        g_w1h[i] = __float2half_rn(aW1[i]);
}

// ---------------------------------------------------------------------------
// Kernel 1: fused attention-score MLP, plain fp16 HMMA, A+B double-buffered,
// ONE barrier per K-chunk with race-free ordering:
//   store A -> wait_group 0 -> barrier -> issue loadB(c+1) -> ldmatrix/MMA.
// B-writes for c+1 land after barrier(c) (prior-stage reads done); B-reads of
// chunk c were issued at c-1, waited per-warp, published by barrier(c).
// ---------------------------------------------------------------------------
__global__ __launch_bounds__(256) void attn_kernel(
    const float* __restrict__ x,
    const float* __restrict__ ab1,
    const float* __restrict__ aW2,
    const float* __restrict__ ab2,
    float* __restrict__ wout)
{
    __shared__ __align__(16) __half Ah[2][BM][40];
    __shared__ __align__(16) __half Bh[2][BK][72];
    __shared__ float red[128][2];

    const int tid   = threadIdx.x;
    const int lane  = tid & 31;
    const int warp  = tid >> 5;
    const int warpM = warp >> 1;
    const int warpN = warp & 1;
    const long rowBase = (long)blockIdx.x * BM;
    const float* xb = x + rowBase * DIM;

    float acc[2][4][4];
    #pragma unroll
    for (int mi = 0; mi < 2; mi++)
        #pragma unroll
        for (int ni = 0; ni < 4; ni++)
            #pragma unroll
            for (int q = 0; q < 4; q++) acc[mi][ni][q] = 0.f;

    auto loadB = [&](int s, int c) {
        int r = tid >> 3, g = tid & 7;
        uint32_t dh = (uint32_t)__cvta_generic_to_shared(&Bh[s][r][g * 8]);
        cp16(dh, g_w1h + (c * BK + r) * HID + g * 8);
        asm volatile("cp.async.commit_group;");
    };

    const int ar = tid >> 1;
    const int ah = tid & 1;
    const float* xrow = xb + (long)ar * DIM + ah * 16;

    loadB(0, 0);   // prologue: group for chunk 0 in flight
    float4 xr[4];
    #pragma unroll
    for (int q = 0; q < 4; q++)
        xr[q] = *reinterpret_cast<const float4*>(xrow + q * 4);

    for (int c = 0; c < NCH; c++) {
        const int st = c & 1;
        // convert 16 floats -> 8 packed half2
        unsigned hw[8];
        const float* xv = reinterpret_cast<const float*>(xr);
        #pragma unroll
        for (int e = 0; e < 8; e++) {
            __half2 hp = __float22half2_rn(make_float2(xv[2 * e], xv[2 * e + 1]));
            hw[e] = *reinterpret_cast<unsigned*>(&hp);
        }
        float4 xn[4];
        if (c + 1 < NCH) {
            #pragma unroll
            for (int q = 0; q < 4; q++)
                xn[q] = *reinterpret_cast<const float4*>(xrow + (c + 1) * BK + q * 4);
        }
        // store A stage st (safe: stage-st reads at c-2 precede barrier(c-1))
        {
            char* pa = reinterpret_cast<char*>(&Ah[st][0][0]) + ar * 80 + ah * 32;
            *reinterpret_cast<uint4*>(pa)      = make_uint4(hw[0], hw[1], hw[2], hw[3]);
            *reinterpret_cast<uint4*>(pa + 16) = make_uint4(hw[4], hw[5], hw[6], hw[7]);
        }
        // chunk c's B group (issued last iteration / prologue) completes here
        asm volatile("cp.async.wait_group 0;");
        __syncthreads();   // publishes A stores + B chunk c; orders prior reads
        // issue next B load AFTER the barrier (prior-stage reads are done)
        if (c + 1 < NCH)
            loadB((c + 1) & 1, c + 1);

        #pragma unroll
        for (int ks = 0; ks < 2; ks++) {
            const int k0 = ks * 16;
            unsigned Ahf[2][4];
            #pragma unroll
            for (int mi = 0; mi < 2; mi++) {
                int arow2 = warpM * 32 + mi * 16 + (lane & 15);
                int acol  = k0 + ((lane >> 4) << 3);
                uint32_t base = (uint32_t)__cvta_generic_to_shared(&Ah[st][arow2][acol]);
                ldm_x4(Ahf[mi], base);
            }
            unsigned Bhf[4][2];
            #pragma unroll
            for (int pr = 0; pr < 2; pr++) {
                int brow = k0 + (lane & 15);
                int bcol = warpN * 32 + pr * 16 + ((lane >> 4) << 3);
                unsigned t4[4];
                uint32_t bb = (uint32_t)__cvta_generic_to_shared(&Bh[st][brow][bcol]);
                ldm_x4t(t4, bb);
                Bhf[pr * 2][0] = t4[0]; Bhf[pr * 2][1] = t4[1];
                Bhf[pr * 2 + 1][0] = t4[2]; Bhf[pr * 2 + 1][1] = t4[3];
            }
            #pragma unroll
            for (int mi = 0; mi < 2; mi++)
                #pragma unroll
                for (int ni = 0; ni < 4; ni++)
                    hmma(acc[mi][ni], Ahf[mi], Bhf[ni]);
        }
        #pragma unroll
        for (int q = 0; q < 4; q++) xr[q] = xn[q];
    }

    const int lk = lane & 3;
    const int lr = lane >> 2;
    float b1v[4][2], w2v[4][2];
    #pragma unroll
    for (int ni = 0; ni < 4; ni++) {
        int col = warpN * 32 + ni * 8 + 2 * lk;
        b1v[ni][0] = ab1[col];     b1v[ni][1] = ab1[col + 1];
        w2v[ni][0] = aW2[col];     w2v[ni][1] = aW2[col + 1];
    }
    float p[2][2] = {{0.f, 0.f}, {0.f, 0.f}};
    #pragma unroll
    for (int mi = 0; mi < 2; mi++)
        #pragma unroll
        for (int ni = 0; ni < 4; ni++) {
            p[mi][0] += gelu_f(acc[mi][ni][0] + b1v[ni][0]) * w2v[ni][0]
                      + gelu_f(acc[mi][ni][1] + b1v[ni][1]) * w2v[ni][1];
            p[mi][1] += gelu_f(acc[mi][ni][2] + b1v[ni][0]) * w2v[ni][0]
                      + gelu_f(acc[mi][ni][3] + b1v[ni][1]) * w2v[ni][1];
        }
    #pragma unroll
    for (int mi = 0; mi < 2; mi++)
        #pragma unroll
        for (int h = 0; h < 2; h++) {
            p[mi][h] += __shfl_xor_sync(0xffffffffu, p[mi][h], 1);
            p[mi][h] += __shfl_xor_sync(0xffffffffu, p[mi][h], 2);
        }
    if (lk == 0) {
        #pragma unroll
        for (int mi = 0; mi < 2; mi++) {
            int r = warpM * 32 + mi * 16 + lr;
            red[r][warpN]     = p[mi][0];
            red[r + 8][warpN] = p[mi][1];
        }
    }
    __syncthreads();
    if (tid < 128) {
        float s = red[tid][0] + red[tid][1] + ab2[0];
        wout[rowBase + tid] = 1.0f / (1.0f + expf(-s));
    }
}

// ---------------------------------------------------------------------------
// Kernel 2: radix-select with parallel suffix-scan bucket pick.
// ---------------------------------------------------------------------------
__global__ __launch_bounds__(512) void select_kernel(const float* __restrict__ w)
{
    __shared__ unsigned sv[NINST];
    __shared__ int hist[16][256];
    __shared__ int scan[256];
    __shared__ unsigned s_prefix;
    __shared__ int s_k, s_above, s_cnt;

    const int b = blockIdx.x;
    const int tid = threadIdx.x;
    const int wid = tid >> 5;
    const float* wb = w + b * NINST;

    for (int i = tid; i < NINST; i += 512)
        sv[i] = __float_as_uint(wb[i]);
    if (tid == 0) { s_prefix = 0u; s_k = TOPK_K; s_above = 0; s_cnt = 0; }
    __syncthreads();

    for (int r = 0; r < 4; r++) {
        for (int i = tid; i < 16 * 256; i += 512)
            hist[i >> 8][i & 255] = 0;
        __syncthreads();
        const unsigned pref = s_prefix;
        const int k = s_k;
        const int sh = 24 - 8 * r;
        for (int i = tid; i < NINST; i += 512) {
            unsigned v = sv[i];
            bool ok = (r == 0) || ((v >> (sh + 8)) == pref);
            if (ok) atomicAdd(&hist[wid][(v >> sh) & 255], 1);
        }
        __syncthreads();
        if (tid < 256) {
            int s = hist[0][tid];
            #pragma unroll
            for (int h = 1; h < 16; h++) s += hist[h][tid];
            scan[tid] = s;
        }
        __syncthreads();
        // suffix sums (count of elements in buckets >= i)
        #pragma unroll
        for (int off = 1; off < 256; off <<= 1) {
            int add = 0;
            if (tid < 256 && tid + off < 256) add = scan[tid + off];
            __syncthreads();
            if (tid < 256) scan[tid] += add;
            __syncthreads();
        }
        if (tid < 256) {
            int cumi  = scan[tid];
            int cumnx = (tid == 255) ? 0 : scan[tid + 1];
            if (cumi >= k && cumnx < k) {
                s_prefix = (pref << 8) | (unsigned)tid;
                s_k = k - cumnx;
            }
        }
        __syncthreads();
    }

    const float t   = __uint_as_float(s_prefix);
    const float thi = t + BAND;
    const float tlo = t - BAND;

    int la = 0;
    for (int i = tid; i < NINST; i += 512) {
        float wv = __uint_as_float(sv[i]);
        g_flag[b * NINST + i] = 0;
        if (wv > thi) la++;
        else if (wv >= tlo) {
            int p = atomicAdd(&s_cnt, 1);
            if (p < CAP) g_cand[b][p] = i;
        }
    }
    atomicAdd(&s_above, la);
    __syncthreads();
    if (tid == 0) {
        g_thr[b]   = s_prefix;
        g_above[b] = s_above;
        g_ccnt[b]  = s_cnt < CAP ? s_cnt : CAP;
    }
}

// ---------------------------------------------------------------------------
// Kernel 3: exact fp32 score recompute for band candidates.
// ---------------------------------------------------------------------------
__global__ __launch_bounds__(256) void refine_kernel(
    const float* __restrict__ x,  const float* __restrict__ aW1,
    const float* __restrict__ ab1, const float* __restrict__ aW2,
    const float* __restrict__ ab2)
{
    const int b = blockIdx.y;
    const int cnt = g_ccnt[b];
    __shared__ float sx[DIM];
    __shared__ float sh4[4][64];
    __shared__ float sr[2];
    const int tid = threadIdx.x;
    const int q = tid >> 6;       // K quarter
    const int j = tid & 63;       // hidden unit

    for (int ci = blockIdx.x; ci < cnt; ci += 64) {
        const int idx = g_cand[b][ci];
        const float* xr = x + ((long)b * NINST + idx) * DIM;
        sx[tid]       = xr[tid];
        sx[tid + 256] = xr[tid + 256];
        __syncthreads();

        const float* wp = aW1 + (long)(q * 128) * HID + j;
        const float* xq = sx + q * 128;
        float acc = 0.f;
        #pragma unroll
        for (int g0 = 0; g0 < 128; g0 += 16) {
            float wv[16];
            #pragma unroll
            for (int t = 0; t < 16; t++)
                wv[t] = wp[(long)(g0 + t) * HID];
            #pragma unroll
            for (int t = 0; t < 16; t++)
                acc += xq[g0 + t] * wv[t];
        }
        sh4[q][j] = acc;
        __syncthreads();

        if (tid < 64) {
            float hsum = sh4[0][j] + sh4[1][j] + sh4[2][j] + sh4[3][j];
            float hv = gelu_f(hsum + ab1[j]) * aW2[j];
            #pragma unroll
            for (int off = 16; off >= 1; off >>= 1)
                hv += __shfl_down_sync(0xffffffffu, hv, off);
            if ((j & 31) == 0) sr[j >> 5] = hv;
        }
        __syncthreads();
        if (tid == 0) {
            float logit = sr[0] + sr[1] + ab2[0];
            g_cval[b][ci] = 1.0f / (1.0f + expf(-logit));
        }
        __syncthreads();
    }
}

// ---------------------------------------------------------------------------
// Kernel 4: exact ranking among candidates -> flags (value desc, index asc).
// ---------------------------------------------------------------------------
__global__ __launch_bounds__(256) void finalize_kernel()
{
    __shared__ float v[CAP];
    __shared__ int  ix[CAP];
    const int b = blockIdx.x;
    const int tid = threadIdx.x;
    const int cnt  = g_ccnt[b];
    const int need = TOPK_K - g_above[b];

    for (int i = tid; i < cnt; i += 256) { v[i] = g_cval[b][i]; ix[i] = g_cand[b][i]; }
    __syncthreads();
    for (int i = tid; i < cnt; i += 256) {
        float vi = v[i]; int xi = ix[i];
        int rank = 0;
        for (int j = 0; j < cnt; j++)
            rank += (v[j] > vi) || (v[j] == vi && ix[j] < xi);
        if (rank < need) g_flag[b * NINST + xi] = 1;
    }
}

// ---------------------------------------------------------------------------
// Kernel 5: weighted gather-sum with per-block index compaction.
// ---------------------------------------------------------------------------
__global__ __launch_bounds__(128) void gather_kernel(
    const float* __restrict__ x, const float* __restrict__ w)
{
    __shared__ int   sel[GROWS];
    __shared__ float sw[GROWS];
    __shared__ int   wbase[4];
    __shared__ int   scount;

    const int b  = blockIdx.y;
    const int rc = blockIdx.x;
    const int r0 = rc * GROWS;
    const int tid = threadIdx.x;
    const int lane = tid & 31;
    const int wrp = tid >> 5;

    const float thi = __uint_as_float(g_thr[b]) + BAND;

    float wi = w[b * NINST + r0 + tid];
    bool pick = (wi > thi) || g_flag[b * NINST + r0 + tid];
    unsigned mask = __ballot_sync(0xffffffffu, pick);
    int wcnt = __popc(mask);
    if (lane == 0) wbase[wrp] = wcnt;
    __syncthreads();
    if (tid == 0) {
        int s = 0;
        #pragma unroll
        for (int q = 0; q < 4; q++) { int c = wbase[q]; wbase[q] = s; s += c; }
        scount = s;
    }
    __syncthreads();
    if (pick) {
        int pos = wbase[wrp] + __popc(mask & ((1u << lane) - 1u));
        sel[pos] = tid;
        sw[pos]  = wi;
    }
    __syncthreads();

    const int d4 = tid * 4;
    const int nsel = scount;
    const float* xb = x + ((long)b * NINST + r0) * DIM + d4;

    float4 acc = make_float4(0.f, 0.f, 0.f, 0.f);
    for (int s = 0; s < nsel; s++) {
        float ws = sw[s];
        float4 xv = *reinterpret_cast<const float4*>(xb + (long)sel[s] * DIM);
        acc.x += ws * xv.x; acc.y += ws * xv.y;
        acc.z += ws * xv.z; acc.w += ws * xv.w;
    }
    *reinterpret_cast<float4*>(&g_part[(rc * BATCH + b) * DIM + d4]) = acc;
}

// ---------------------------------------------------------------------------
// Kernel 6: mlp1 split-K partials with inline emb reduction.
// ---------------------------------------------------------------------------
__global__ __launch_bounds__(128) void mlp1_part_kernel(
    const float* __restrict__ W, float* __restrict__ part)
{
    __shared__ float s_in[BATCH][KLEN];
    const int kc = blockIdx.y;
    const int j  = blockIdx.x * 128 + threadIdx.x;

    #pragma unroll
    for (int it = 0; it < (BATCH * KLEN) / 128; it++) {
        int i = it * 128 + threadIdx.x;
        int bb = i / KLEN, dd = i % KLEN;
        const float* p = g_part + bb * DIM + kc * KLEN + dd;
        float s0 = 0.f, s1 = 0.f;
        #pragma unroll
        for (int rc = 0; rc < GCHUNKS; rc += 2) {
            s0 += p[(long)rc * BATCH * DIM];
            s1 += p[(long)(rc + 1) * BATCH * DIM];
        }
        s_in[bb][dd] = (s0 + s1) * (1.0f / (float)TOPK_K);
    }
    __syncthreads();

    float acc[BATCH];
    #pragma unroll
    for (int bb = 0; bb < BATCH; bb++) acc[bb] = 0.f;

    #pragma unroll 4
    for (int dd = 0; dd < KLEN; dd++) {
        float wv = W[(long)(kc * KLEN + dd) * DIM + j];
        #pragma unroll
        for (int bb = 0; bb < BATCH; bb++)
            acc[bb] += s_in[bb][dd] * wv;
    }
    #pragma unroll
    for (int bb = 0; bb < BATCH; bb++)
        part[(kc * BATCH + bb) * DIM + j] = acc[bb];
}

// ---------------------------------------------------------------------------
// Kernel 7: mlp2 split-K partials with inline (reduce p1 + bias + gelu).
// ---------------------------------------------------------------------------
__global__ __launch_bounds__(128) void mlp2_part_kernel(
    const float* __restrict__ W, const float* __restrict__ b1,
    float* __restrict__ part)
{
    __shared__ float s_in[BATCH][KLEN];
    const int kc = blockIdx.y;
    const int j  = blockIdx.x * 128 + threadIdx.x;

    #pragma unroll
    for (int it = 0; it < (BATCH * KLEN) / 128; it++) {
        int i = it * 128 + threadIdx.x;
        int bb = i / KLEN, dd = i % KLEN;
        const float* p = g_p1 + bb * DIM + kc * KLEN + dd;
        float s = 0.f;
        #pragma unroll
        for (int c = 0; c < KCHUNKS; c++)
            s += p[(long)c * BATCH * DIM];
        s_in[bb][dd] = gelu_f(s + b1[kc * KLEN + dd]);
    }
    __syncthreads();

    float acc[BATCH];
    #pragma unroll
    for (int bb = 0; bb < BATCH; bb++) acc[bb] = 0.f;

    #pragma unroll 4
    for (int dd = 0; dd < KLEN; dd++) {
        float wv = W[(long)(kc * KLEN + dd) * DIM + j];
        #pragma unroll
        for (int bb = 0; bb < BATCH; bb++)
            acc[bb] += s_in[bb][dd] * wv;
    }
    #pragma unroll
    for (int bb = 0; bb < BATCH; bb++)
        part[(kc * BATCH + bb) * DIM + j] = acc[bb];
}

// ---------------------------------------------------------------------------
// Kernel 8: reduce mlp2 partials + bias -> out.
// ---------------------------------------------------------------------------
__global__ __launch_bounds__(512) void mlp2_reduce_kernel(
    const float* __restrict__ bias, float* __restrict__ out)
{
    const int b = blockIdx.x;
    const int j = threadIdx.x;
    float s = 0.f;
    #pragma unroll
    for (int kc = 0; kc < KCHUNKS; kc++)
        s += g_p2[(kc * BATCH + b) * DIM + j];
    out[b * DIM + j] = s + bias[j];
}

// ---------------------------------------------------------------------------
extern "C" void kernel_launch(void* const* d_in, const int* in_sizes, int n_in,
                              void* d_out, int out_size)
{
    const float* x   = (const float*)d_in[0];
    const float* aW1 = (const float*)d_in[1];
    const float* ab1 = (const float*)d_in[2];
    const float* aW2 = (const float*)d_in[3];
    const float* ab2 = (const float*)d_in[4];
    const float* pW1 = (const float*)d_in[5];
    const float* pb1 = (const float*)d_in[6];
    const float* pW2 = (const float*)d_in[7];
    const float* pb2 = (const float*)d_in[8];

    float* out = (float*)d_out;
    float* proj    = out;                 // [B, DIM]
    float* weights = out + BATCH * DIM;   // [B, NINST]

    float* d_p1;  cudaGetSymbolAddress((void**)&d_p1, g_p1);
    float* d_p2;  cudaGetSymbolAddress((void**)&d_p2, g_p2);

    conv_w1_kernel<<<(DIM * HID + 255) / 256, 256>>>(aW1);
    attn_kernel<<<(BATCH * NINST) / BM, 256>>>(x, ab1, aW2, ab2, weights);
    select_kernel<<<BATCH, 512>>>(weights);
    refine_kernel<<<dim3(64, BATCH), 256>>>(x, aW1, ab1, aW2, ab2);
    finalize_kernel<<<BATCH, 256>>>();
    gather_kernel<<<dim3(GCHUNKS, BATCH), 128>>>(x, weights);
    mlp1_part_kernel<<<dim3(DIM / 128, KCHUNKS), 128>>>(pW1, d_p1);
    mlp2_part_kernel<<<dim3(DIM / 128, KCHUNKS), 128>>>(pW2, pb1, d_p2);
    mlp2_reduce_kernel<<<BATCH, 512>>>(pb2, proj);
}